// round 1
// baseline (speedup 1.0000x reference)
#include <cuda_runtime.h>
#include <math.h>
#include <stdint.h>

#define G 64
#define NN 1000
#define EE 8192
#define C 128
#define HIDN 256
#define NCLS 2

// ---------------- scratch (device globals; no allocation allowed) ----------------
__device__ float g_bufA[(size_t)G * NN * C];   // 32.8 MB
__device__ float g_bufB[(size_t)G * NN * C];   // 32.8 MB
__device__ int   g_deg[G * NN];
__device__ float g_dinv[G * NN];
__device__ int   g_rowptr[G * (NN + 1)];
__device__ int   g_cursor[G * NN];
__device__ int   g_csrsrc[G * EE];
__device__ float g_gvec[G * C];
__device__ float g_qkv[G * 3 * C];
__device__ float g_nrepr[C];

// ---------------- graph prep ----------------
__global__ void zero_deg_kernel() {
    int i = blockIdx.x * blockDim.x + threadIdx.x;
    if (i < G * NN) g_deg[i] = 0;
}

__global__ void count_deg_kernel(const int* __restrict__ ei) {
    int idx = blockIdx.x * blockDim.x + threadIdx.x;
    if (idx >= G * EE) return;
    int g = idx >> 13;           // /EE
    int e = idx & (EE - 1);
    int dst = ei[(size_t)g * 2 * EE + EE + e];
    atomicAdd(&g_deg[g * NN + dst], 1);
}

// block per graph: inclusive scan of deg -> rowptr, cursor, dinv; zero gvec/nrepr
__global__ void scan_kernel() {
    __shared__ int s[1024];
    int g = blockIdx.x;
    int t = threadIdx.x;
    int d = (t < NN) ? g_deg[g * NN + t] : 0;
    s[t] = d;
    __syncthreads();
    for (int off = 1; off < 1024; off <<= 1) {
        int v = (t >= off) ? s[t - off] : 0;
        __syncthreads();
        s[t] += v;
        __syncthreads();
    }
    if (t < NN) {
        g_rowptr[g * (NN + 1) + t + 1] = s[t];
        g_cursor[g * NN + t] = s[t] - d;          // exclusive start
        g_dinv[g * NN + t] = rsqrtf((float)d + 1.0f);
    }
    if (t == 0) g_rowptr[g * (NN + 1)] = 0;
    if (t < C) g_gvec[g * C + t] = 0.0f;
    if (g == 0 && t < C) g_nrepr[t] = 0.0f;
}

__global__ void csr_fill_kernel(const int* __restrict__ ei) {
    int idx = blockIdx.x * blockDim.x + threadIdx.x;
    if (idx >= G * EE) return;
    int g = idx >> 13;
    int e = idx & (EE - 1);
    int src = ei[(size_t)g * 2 * EE + e];
    int dst = ei[(size_t)g * 2 * EE + EE + e];
    int pos = atomicAdd(&g_cursor[g * NN + dst], 1);
    g_csrsrc[g * EE + pos] = src;
}

// ---------------- fp32 GEMM: (64000 x 128) @ (128 x 128) ----------------
// Block: 64 rows x full 128 cols, 256 threads, each thread 4x8 outputs.
#define XS_STRIDE 132
__global__ void gemm_kernel(const float* __restrict__ X, const float* __restrict__ W,
                            float* __restrict__ Y) {
    extern __shared__ float smem[];
    float* Xs = smem;                    // [64][132]
    float* Ws = smem + 64 * XS_STRIDE;   // [128][128]
    int rowBase = blockIdx.x * 64;
    int tid = threadIdx.x;

    const float4* W4 = (const float4*)W;
    float4* Ws4 = (float4*)Ws;
    for (int i = tid; i < (128 * 128) / 4; i += 256) Ws4[i] = W4[i];

    for (int i = tid; i < (64 * 128) / 4; i += 256) {
        int r = i >> 5;           // 32 float4 per row
        int c4 = i & 31;
        float4 v = ((const float4*)(X + (size_t)(rowBase + r) * C))[c4];
        ((float4*)(Xs + r * XS_STRIDE))[c4] = v;
    }
    __syncthreads();

    int tx = tid & 15, ty = tid >> 4;
    int r0 = ty * 4, c0 = tx * 8;
    float acc[4][8];
#pragma unroll
    for (int i = 0; i < 4; i++)
#pragma unroll
        for (int j = 0; j < 8; j++) acc[i][j] = 0.0f;

#pragma unroll 4
    for (int k = 0; k < 128; k++) {
        float4 b0 = *(const float4*)(Ws + k * 128 + c0);
        float4 b1 = *(const float4*)(Ws + k * 128 + c0 + 4);
#pragma unroll
        for (int i = 0; i < 4; i++) {
            float a = Xs[(r0 + i) * XS_STRIDE + k];
            acc[i][0] += a * b0.x; acc[i][1] += a * b0.y;
            acc[i][2] += a * b0.z; acc[i][3] += a * b0.w;
            acc[i][4] += a * b1.x; acc[i][5] += a * b1.y;
            acc[i][6] += a * b1.z; acc[i][7] += a * b1.w;
        }
    }

#pragma unroll
    for (int i = 0; i < 4; i++) {
        float* yr = Y + (size_t)(rowBase + r0 + i) * C + c0;
        float4 v0 = make_float4(acc[i][0], acc[i][1], acc[i][2], acc[i][3]);
        float4 v1 = make_float4(acc[i][4], acc[i][5], acc[i][6], acc[i][7]);
        ((float4*)yr)[0] = v0;
        ((float4*)yr)[1] = v1;
    }
}

// ---------------- aggregation: warp per destination node (CSR gather) ----------------
__global__ void agg_kernel(const float* __restrict__ h, float* __restrict__ out,
                           const float* __restrict__ bias) {
    int warp = threadIdx.x >> 5;
    int lane = threadIdx.x & 31;
    int gn = blockIdx.x * 8 + warp;     // 0..63999
    int g = gn / NN;
    int n = gn - g * NN;

    int base = g * (NN + 1) + n;
    int st = g_rowptr[base];
    int en = g_rowptr[base + 1];
    float dn = g_dinv[g * NN + n];

    float a0 = 0.f, a1 = 0.f, a2 = 0.f, a3 = 0.f;
    const float* hb = h + (size_t)g * NN * C;
    for (int e = st; e < en; e++) {
        int s = g_csrsrc[g * EE + e];
        float w = g_dinv[g * NN + s] * dn;
        const float* hr = hb + (size_t)s * C;
        a0 += hr[lane]      * w;
        a1 += hr[lane + 32] * w;
        a2 += hr[lane + 64] * w;
        a3 += hr[lane + 96] * w;
    }
    const float* hs = hb + (size_t)n * C;
    float d2 = dn * dn;
    a0 = tanhf(a0 + hs[lane]      * d2 + bias[lane]);
    a1 = tanhf(a1 + hs[lane + 32] * d2 + bias[lane + 32]);
    a2 = tanhf(a2 + hs[lane + 64] * d2 + bias[lane + 64]);
    a3 = tanhf(a3 + hs[lane + 96] * d2 + bias[lane + 96]);

    float* orow = out + (size_t)gn * C;
    orow[lane]      = a0;
    orow[lane + 32] = a1;
    orow[lane + 64] = a2;
    orow[lane + 96] = a3;
}

// ---------------- graph sum: gvec[g][c] = sum_n bufB[g][n][c] ----------------
__global__ void gsum_kernel(const float* __restrict__ buf) {
    int g = blockIdx.x;
    int p = blockIdx.y;      // 10 parts of 100 nodes
    int c = threadIdx.x;
    float acc = 0.f;
    const float* b = buf + ((size_t)g * NN + p * 100) * C + c;
    for (int n = 0; n < 100; n++) acc += b[(size_t)n * C];
    atomicAdd(&g_gvec[g * C + c], acc);
}

// ---------------- qkv: one block per graph-row ----------------
__global__ void qkv_kernel(const float* __restrict__ in_w, const float* __restrict__ in_b) {
    int bi = blockIdx.x;
    int tid = threadIdx.x;       // 384 threads
    __shared__ float gr[C];
    if (tid < C) gr[tid] = g_gvec[bi * C + tid];
    __syncthreads();
    float acc = in_b[tid];
    const float* wr = in_w + (size_t)tid * C;
#pragma unroll 4
    for (int c = 0; c < C; c++) acc += gr[c] * wr[c];
    g_qkv[bi * 3 * C + tid] = acc;
}

// ---------------- attention + out-proj + MLP + LN + relu-sum ----------------
__device__ __forceinline__ float blksum128(float v, float* red) {
#pragma unroll
    for (int o = 16; o > 0; o >>= 1) v += __shfl_down_sync(0xffffffffu, v, o);
    if ((threadIdx.x & 31) == 0) red[threadIdx.x >> 5] = v;
    __syncthreads();
    float s = red[0] + red[1] + red[2] + red[3];
    __syncthreads();
    return s;
}

__global__ void tail_kernel(const float* __restrict__ out_w, const float* __restrict__ out_b,
                            const float* __restrict__ ln_g, const float* __restrict__ ln_b,
                            const float* __restrict__ mw1, const float* __restrict__ mb1,
                            const float* __restrict__ mw2, const float* __restrict__ mb2) {
    int bi = blockIdx.x;
    int tid = threadIdx.x;       // 128 threads
    __shared__ float kv[64 * C];
    __shared__ float qrow[C], sc[4 * 64], orow[C], o2row[C], hid[HIDN];
    __shared__ float red[4];

    // load K
    for (int i = tid; i < 64 * C; i += 128) {
        int r = i >> 7, c = i & 127;
        kv[i] = g_qkv[r * 3 * C + C + c];
    }
    qrow[tid] = g_qkv[bi * 3 * C + tid];
    __syncthreads();

    // scores (4 heads x 64 keys), scaled by 1/sqrt(32)
    for (int s = tid; s < 256; s += 128) {
        int h = s >> 6, k = s & 63;
        const float* kr = kv + k * C + h * 32;
        const float* qr = qrow + h * 32;
        float a = 0.f;
#pragma unroll
        for (int dd = 0; dd < 32; dd++) a += qr[dd] * kr[dd];
        sc[s] = a * 0.17677669529663687f;
    }
    __syncthreads();

    // softmax per head (serial per head; tiny)
    if (tid < 4) {
        float m = -1e30f;
        for (int k = 0; k < 64; k++) m = fmaxf(m, sc[tid * 64 + k]);
        float ssum = 0.f;
        for (int k = 0; k < 64; k++) { float e = expf(sc[tid * 64 + k] - m); sc[tid * 64 + k] = e; ssum += e; }
        float inv = 1.0f / ssum;
        for (int k = 0; k < 64; k++) sc[tid * 64 + k] *= inv;
    }
    __syncthreads();

    // load V over K
    for (int i = tid; i < 64 * C; i += 128) {
        int r = i >> 7, c = i & 127;
        kv[i] = g_qkv[r * 3 * C + 2 * C + c];
    }
    __syncthreads();

    // o[c] = sum_k attn[h][k] * v[k][c]
    {
        int c = tid, h = c >> 5;
        float a = 0.f;
        for (int k = 0; k < 64; k++) a += sc[h * 64 + k] * kv[k * C + c];
        orow[c] = a;
    }
    __syncthreads();

    // out projection: o2[j] = sum_c o[c]*out_w[j][c] + out_b[j]
    {
        int j = tid;
        float a = out_b[j];
        const float* wr = out_w + (size_t)j * C;
#pragma unroll 4
        for (int c = 0; c < C; c++) a += orow[c] * wr[c];
        o2row[j] = a;
    }
    __syncthreads();

    // mlp hidden
    for (int j = tid; j < HIDN; j += 128) {
        float a = mb1[j];
        for (int c = 0; c < C; c++) a += o2row[c] * mw1[c * HIDN + j];
        hid[j] = fmaxf(a, 0.f);
    }
    __syncthreads();

    // mlp out + residual + LN + relu + accumulate
    float y;
    {
        int c = tid;
        float a = mb2[c];
        for (int j = 0; j < HIDN; j++) a += hid[j] * mw2[j * C + c];
        y = o2row[c] + a;
    }
    float mu = blksum128(y, red) * (1.0f / 128.0f);
    float d = y - mu;
    float var = blksum128(d * d, red) * (1.0f / 128.0f);
    float yn = d * rsqrtf(var + 1e-5f) * ln_g[tid] + ln_b[tid];
    atomicAdd(&g_nrepr[tid], fmaxf(yn, 0.f));
}

__global__ void final_kernel(const float* __restrict__ lw, const float* __restrict__ lb,
                             float* __restrict__ out) {
    int tid = threadIdx.x;
    if (tid < NCLS) {
        float a = lb[tid];
        for (int c = 0; c < C; c++) a += g_nrepr[c] * lw[c * NCLS + tid];
        out[tid] = a;
    }
}

// ---------------- launch ----------------
extern "C" void kernel_launch(void* const* d_in, const int* in_sizes, int n_in,
                              void* d_out, int out_size) {
    const float* x     = (const float*)d_in[0];
    const int*   ei    = (const int*)d_in[1];
    const float* W0    = (const float*)d_in[2];
    const float* b0    = (const float*)d_in[3];
    const float* W1    = (const float*)d_in[4];
    const float* b1    = (const float*)d_in[5];
    const float* in_w  = (const float*)d_in[6];
    const float* in_b  = (const float*)d_in[7];
    const float* out_w = (const float*)d_in[8];
    const float* out_b = (const float*)d_in[9];
    const float* ln2_g = (const float*)d_in[10];
    const float* ln2_b = (const float*)d_in[11];
    const float* mw1   = (const float*)d_in[12];
    const float* mb1   = (const float*)d_in[13];
    const float* mw2   = (const float*)d_in[14];
    const float* mb2   = (const float*)d_in[15];
    const float* lw    = (const float*)d_in[16];
    const float* lb    = (const float*)d_in[17];
    float* out = (float*)d_out;

    float *bufA, *bufB;
    cudaGetSymbolAddress((void**)&bufA, g_bufA);
    cudaGetSymbolAddress((void**)&bufB, g_bufB);

    int gemm_smem = (64 * XS_STRIDE + 128 * 128) * sizeof(float);
    cudaFuncSetAttribute(gemm_kernel, cudaFuncAttributeMaxDynamicSharedMemorySize, gemm_smem);

    zero_deg_kernel<<<(G * NN + 255) / 256, 256>>>();
    count_deg_kernel<<<(G * EE) / 256, 256>>>(ei);
    scan_kernel<<<G, 1024>>>();
    csr_fill_kernel<<<(G * EE) / 256, 256>>>(ei);

    gemm_kernel<<<(G * NN) / 64, 256, gemm_smem>>>(x, W0, bufA);
    agg_kernel<<<(G * NN) / 8, 256>>>(bufA, bufB, b0);
    gemm_kernel<<<(G * NN) / 64, 256, gemm_smem>>>(bufB, W1, bufA);
    agg_kernel<<<(G * NN) / 8, 256>>>(bufA, bufB, b1);

    gsum_kernel<<<dim3(G, 10), C>>>(bufB);
    qkv_kernel<<<G, 3 * C>>>(in_w, in_b);
    tail_kernel<<<G, C>>>(out_w, out_b, ln2_g, ln2_b, mw1, mb1, mw2, mb2);
    final_kernel<<<1, 32>>>(lw, lb, out);
}